// round 9
// baseline (speedup 1.0000x reference)
#include <cuda_runtime.h>

#define KCLS   128
#define DDIM   64
#define BROWS  512
#define NTH    512
#define NWARP  16
#define GRID_MAIN 304
#define PART_STRIDE 8448        // 8192 sums + 128 cnt + 128 ssq
#define PAIRBLKS 16
#define WLCAP  112              // used region <= 96 + pad(7) + lookahead(8)
#define WLMAX  96

// dynamic smem layout for k_main (bytes)
// acc4 : float4[2][129][16] = 66048   (per-half-warp class sum accumulators)
// cs   : float2[2][129]     = 2064    (per-half-warp {count, sumsq} per class)
// wl   : int   [16][112]    = 7168
#define OFF_ACC4  0
#define OFF_CS    66048
#define OFF_WL    68112
#define SMEM_MAIN 75280

__device__ float g_part[GRID_MAIN * PART_STRIDE];
__device__ float g_centers[KCLS * DDIM];
__device__ float g_sqn[KCLS];
__device__ float g_cntk[KCLS];
__device__ float g_ivar, g_nh2, g_nvalid, g_dsum, g_pcnt;
__device__ unsigned g_ticket;

// ================= main accumulation =================
__global__ void __launch_bounds__(NTH, 2)
k_main(const float4* __restrict__ z4, const int* __restrict__ labels, int nrows) {
    extern __shared__ char sm[];
    float4* acc4 = (float4*)(sm + OFF_ACC4);
    float2* cs   = (float2*)(sm + OFF_CS);
    int*    wlist= (int*)   (sm + OFF_WL);

    const int tid  = threadIdx.x;
    const int warp = tid >> 5;
    const int lane = tid & 31;
    const int hw   = lane >> 4;
    const int hl   = lane & 15;
    const unsigned lt = (1u << lane) - 1u;
    int* wl = wlist + warp * WLCAP;

    if (blockIdx.x == 0 && tid == 0) {
        g_ivar = 0.f; g_nh2 = 0.f; g_nvalid = 0.f;
        g_dsum = 0.f; g_pcnt = 0.f; g_ticket = 0u;
    }

    // zero accumulators (68112 B = 4257 float4)
    {
        float4* p = (float4*)sm;
        const float4 zz = make_float4(0.f, 0.f, 0.f, 0.f);
        for (int i = tid; i < 4257; i += NTH) p[i] = zz;
    }
    __syncthreads();   // last CTA-wide sync until flush

    const int nb = (nrows + BROWS - 1) / BROWS;

    for (int tile = blockIdx.x; tile < nb; tile += GRID_MAIN) {
        const int rowbase = tile * BROWS;

        // ---- load this warp's view of the tile's 512 labels (int4 vectorized) ----
        int4 la[4];
        if (rowbase + BROWS <= nrows) {
            const int4* lab4 = (const int4*)(labels + rowbase);
            #pragma unroll
            for (int v = 0; v < 4; v++) la[v] = lab4[v * 32 + lane];
        } else {
            #pragma unroll
            for (int v = 0; v < 4; v++) {
                int r0 = rowbase + v * 128 + lane * 4;
                la[v].x = (r0     < nrows) ? labels[r0]     : -1;
                la[v].y = (r0 + 1 < nrows) ? labels[r0 + 1] : -1;
                la[v].z = (r0 + 2 < nrows) ? labels[r0 + 2] : -1;
                la[v].w = (r0 + 3 < nrows) ? labels[r0 + 3] : -1;
            }
        }

        // ---- scan: build this warp's worklist ----
        int m = 0;
        #pragma unroll
        for (int v = 0; v < 4; v++) {
            int labs[4] = { la[v].x, la[v].y, la[v].z, la[v].w };
            #pragma unroll
            for (int j = 0; j < 4; j++) {
                int lab = labs[j];
                bool mine = ((unsigned)lab < 128u) && ((lab >> 3) == warp);
                unsigned msk = __ballot_sync(0xffffffffu, mine);
                if (mine) {
                    int idx = m + __popc(msk & lt);
                    if (idx < WLMAX)
                        wl[idx] = ((v * 128 + lane * 4 + j) << 8) | lab;
                }
                m += __popc(msk);
            }
        }
        if (m > WLMAX) m = WLMAX;       // statistically unreachable (11+ sigma)
        const int mpad = (m + 7) & ~7;
        // trash pad: row 0 (always loadable), class 128 (never flushed)
        {
            int j2 = m + lane;
            if (j2 < mpad + 8) wl[j2] = 128;
        }
        __syncwarp();
        if (m == 0) continue;

        // ---- consume: branch-free, depth-4 paired LDG.128 pipeline ----
        const int Ph = mpad >> 1;        // multiple of 4
        float4 q0, q1, q2, q3;
        int e0, e1, e2, e3;

#define FETCH(s, p) do { e##s = wl[2 * (p) + hw]; \
        q##s = __ldcs(&z4[(size_t)(rowbase + (e##s >> 8)) * 16 + hl]); } while (0)
#define CONSUME(s) do { \
        int kk = e##s & 255; \
        int ci = hw * 129 + kk; \
        int ai = ci * 16 + hl; \
        float4 t = acc4[ai]; \
        t.x += q##s.x; t.y += q##s.y; t.z += q##s.z; t.w += q##s.w; \
        acc4[ai] = t; \
        float dot = q##s.x * q##s.x + q##s.y * q##s.y \
                  + q##s.z * q##s.z + q##s.w * q##s.w; \
        dot += __shfl_down_sync(0xffffffffu, dot, 8, 16); \
        dot += __shfl_down_sync(0xffffffffu, dot, 4, 16); \
        dot += __shfl_down_sync(0xffffffffu, dot, 2, 16); \
        dot += __shfl_down_sync(0xffffffffu, dot, 1, 16); \
        if (hl == 0) { \
            float2 cc = cs[ci]; \
            cc.x += 1.f; cc.y += dot; \
            cs[ci] = cc; \
        } \
        FETCH(s, i + 4 + s); } while (0)

        FETCH(0, 0); FETCH(1, 1); FETCH(2, 2); FETCH(3, 3);
        for (int i = 0; i < Ph; i += 4) {
            CONSUME(0); CONSUME(1); CONSUME(2); CONSUME(3);
        }
#undef FETCH
#undef CONSUME
    }

    // ---- flush CTA partials (classes 0..127 only; trash class 128 dropped) ----
    __syncthreads();
    float* Pp = g_part + blockIdx.x * PART_STRIDE;
    float4* P4 = (float4*)Pp;
    for (int idx = tid; idx < KCLS * 16; idx += NTH) {
        int k = idx >> 4, h = idx & 15;
        float4 a = acc4[k * 16 + h];
        float4 b = acc4[(129 + k) * 16 + h];
        a.x += b.x; a.y += b.y; a.z += b.z; a.w += b.w;
        P4[k * 16 + h] = a;
    }
    if (tid < KCLS) {
        float2 a = cs[tid];
        float2 b = cs[129 + tid];
        Pp[8192 + tid] = a.x + b.x;
        Pp[8320 + tid] = a.y + b.y;
    }
}

// ================= per-class reduction =================
__global__ void __launch_bounds__(256) k_mid() {
    const int k = blockIdx.x;
    const int t = threadIdx.x;
    __shared__ float sred[256];
    __shared__ float wcn[8], wsq[8];
    __shared__ float sc[2];
    __shared__ float sq2r[2];

    const int d = t & 63, g = t >> 6;
    float s = 0.f;
    for (int c = g; c < GRID_MAIN; c += 4)
        s += g_part[c * PART_STRIDE + k * 64 + d];
    sred[t] = s;

    float cn = 0.f, sq = 0.f;
    for (int c = t; c < GRID_MAIN; c += 256) {
        cn += g_part[c * PART_STRIDE + 8192 + k];
        sq += g_part[c * PART_STRIDE + 8320 + k];
    }
    #pragma unroll
    for (int o = 16; o; o >>= 1) {
        cn += __shfl_down_sync(0xffffffffu, cn, o);
        sq += __shfl_down_sync(0xffffffffu, sq, o);
    }
    if ((t & 31) == 0) { wcn[t >> 5] = cn; wsq[t >> 5] = sq; }
    __syncthreads();

    if (t == 0) {
        float c0 = 0.f, s0 = 0.f;
        #pragma unroll
        for (int w = 0; w < 8; w++) { c0 += wcn[w]; s0 += wsq[w]; }
        sc[0] = c0; sc[1] = s0;
    }
    __syncthreads();

    const float cnt = sc[0], ssq = sc[1];
    const float safe = fmaxf(cnt, 1.f);

    float sq2 = 0.f;
    if (t < 64) {
        float sum = sred[t] + sred[t + 64] + sred[t + 128] + sred[t + 192];
        float cd = sum / safe;
        g_centers[k * 64 + t] = cd;
        sq2 = cd * cd;
    }
    #pragma unroll
    for (int o = 16; o; o >>= 1) sq2 += __shfl_down_sync(0xffffffffu, sq2, o);
    if (t == 0)  sq2r[0] = sq2;
    if (t == 32) sq2r[1] = sq2;
    __syncthreads();

    if (t == 0) {
        float sqn = sq2r[0] + sq2r[1];
        g_sqn[k] = sqn;
        g_cntk[k] = cnt;
        float var = ssq / safe - sqn;
        if (cnt > 1.f) { atomicAdd(&g_ivar, var); atomicAdd(&g_nh2, 1.f); }
        if (cnt > 0.f) atomicAdd(&g_nvalid, 1.f);
    }
}

// ================= pairwise distances + final loss =================
__global__ void __launch_bounds__(256) k_pair(float* __restrict__ out) {
    __shared__ float c[KCLS * 65];
    __shared__ float cnts[KCLS];
    __shared__ float sqns[KCLS];
    __shared__ float red[256];

    const int t = threadIdx.x;
    for (int idx = t; idx < KCLS * DDIM; idx += 256)
        c[(idx >> 6) * 65 + (idx & 63)] = g_centers[idx];
    if (t < KCLS) { cnts[t] = g_cntk[t]; sqns[t] = g_sqn[t]; }
    __syncthreads();

    float dsum = 0.f, pcnt = 0.f;
    for (int p = blockIdx.x * 256 + t; p < KCLS * KCLS; p += PAIRBLKS * 256) {
        int i = p >> 7, j = p & 127;
        if (j > i && cnts[i] > 0.f && cnts[j] > 0.f) {
            float d0 = 0.f, d1 = 0.f;
            #pragma unroll
            for (int d = 0; d < DDIM; d += 2) {
                d0 = fmaf(c[i * 65 + d],     c[j * 65 + d],     d0);
                d1 = fmaf(c[i * 65 + d + 1], c[j * 65 + d + 1], d1);
            }
            float sq = sqns[i] + sqns[j] - 2.f * (d0 + d1);
            dsum += sqrtf(fmaxf(sq, 0.f));
            pcnt += 1.f;
        }
    }

    red[t] = dsum; __syncthreads();
    for (int s = 128; s; s >>= 1) { if (t < s) red[t] += red[t + s]; __syncthreads(); }
    if (t == 0) atomicAdd(&g_dsum, red[0]);
    __syncthreads();
    red[t] = pcnt; __syncthreads();
    for (int s = 128; s; s >>= 1) { if (t < s) red[t] += red[t + s]; __syncthreads(); }

    if (t == 0) {
        atomicAdd(&g_pcnt, red[0]);
        __threadfence();
        unsigned tk = atomicAdd(&g_ticket, 1u);
        if (tk == PAIRBLKS - 1) {
            float nh2 = g_nh2, nvalid = g_nvalid, ivar = g_ivar;
            float dT = g_dsum, pT = g_pcnt;
            float intra = (nh2 > 0.f) ? ivar / nh2 : 0.f;
            float inter = (pT > 0.f) ? -dT / pT : 0.f;
            float loss = intra + 0.5f * inter;
            out[0] = (nvalid >= 2.f) ? loss : 0.f;
        }
    }
}

// ================= launch =================
extern "C" void kernel_launch(void* const* d_in, const int* in_sizes, int n_in,
                              void* d_out, int out_size) {
    const float4* z4 = (const float4*)d_in[0];
    const int* labels = (const int*)d_in[1];
    int nrows = in_sizes[0] / DDIM;

    cudaFuncSetAttribute(k_main, cudaFuncAttributeMaxDynamicSharedMemorySize,
                         SMEM_MAIN);

    k_main<<<GRID_MAIN, NTH, SMEM_MAIN>>>(z4, labels, nrows);
    k_mid<<<KCLS, 256>>>();
    k_pair<<<PAIRBLKS, 256>>>((float*)d_out);
}

// round 10
// speedup vs baseline: 1.0627x; 1.0627x over previous
#include <cuda_runtime.h>

#define KCLS   128
#define DDIM   64
#define BROWS  512
#define NTH    512
#define NWARP  16
#define GRID_MAIN 304
#define PART_STRIDE 8448        // 8192 sums + 128 cnt + 128 ssq
#define PAIRBLKS 16
#define WLCAP  112
#define WLMAX  96

// dynamic smem layout for k_main (bytes)
// acc4 : float4[2][129][16] = 66048
// acc2 : float [2][129][16] = 16512
// scnt : float [2][130]     = 1040
// wl   : int   [16][112]    = 7168
#define OFF_ACC4  0
#define OFF_ACC2  66048
#define OFF_CNT   82560
#define OFF_WL    83600
#define SMEM_MAIN 90768

__device__ float g_part[GRID_MAIN * PART_STRIDE];
__device__ float g_centers[KCLS * DDIM];
__device__ float g_sqn[KCLS];
__device__ float g_cntk[KCLS];
__device__ float g_ivar, g_nh2, g_nvalid, g_dsum, g_pcnt;
__device__ unsigned g_ticket;

// ================= main accumulation =================
__global__ void __launch_bounds__(NTH, 2)
k_main(const float4* __restrict__ z4, const int* __restrict__ labels, int nrows) {
    extern __shared__ char sm[];
    float4* acc4 = (float4*)(sm + OFF_ACC4);
    float*  acc2 = (float*) (sm + OFF_ACC2);
    float*  scnt = (float*) (sm + OFF_CNT);
    int*    wlist= (int*)   (sm + OFF_WL);

    const int tid  = threadIdx.x;
    const int warp = tid >> 5;
    const int lane = tid & 31;
    const int hw   = lane >> 4;
    const int hl   = lane & 15;
    const unsigned lt = (1u << lane) - 1u;
    int* wl = wlist + warp * WLCAP;

    if (blockIdx.x == 0 && tid == 0) {
        g_ivar = 0.f; g_nh2 = 0.f; g_nvalid = 0.f;
        g_dsum = 0.f; g_pcnt = 0.f; g_ticket = 0u;
    }

    // zero accumulators (83600 B = 5225 float4)
    {
        float4* p = (float4*)sm;
        const float4 zz = make_float4(0.f, 0.f, 0.f, 0.f);
        for (int i = tid; i < 5225; i += NTH) p[i] = zz;
    }
    __syncthreads();   // last CTA-wide sync until flush

    const int nb = (nrows + BROWS - 1) / BROWS;

    // run-merged register accumulator (persists across tiles)
    float4 racc = make_float4(0.f, 0.f, 0.f, 0.f);
    float rssq = 0.f, rcnt = 0.f;
    int curk = -1;

#define FLUSH() do { if (curk >= 0) { \
        int ci = hw * 129 + curk; \
        int ai = ci * 16 + hl; \
        float4 t = acc4[ai]; \
        t.x += racc.x; t.y += racc.y; t.z += racc.z; t.w += racc.w; \
        acc4[ai] = t; \
        acc2[ai] += rssq; \
        if (hl == 0) scnt[hw * 130 + curk] += rcnt; \
        racc = make_float4(0.f, 0.f, 0.f, 0.f); rssq = 0.f; rcnt = 0.f; \
    } } while (0)

    for (int tile = blockIdx.x; tile < nb; tile += GRID_MAIN) {
        const int rowbase = tile * BROWS;

        // ---- labels (int4 vectorized; scalar-guarded only on the last tile) ----
        int4 la[4];
        if (rowbase + BROWS <= nrows) {
            const int4* lab4 = (const int4*)(labels + rowbase);
            #pragma unroll
            for (int v = 0; v < 4; v++) la[v] = lab4[v * 32 + lane];
        } else {
            #pragma unroll
            for (int v = 0; v < 4; v++) {
                int r0 = rowbase + v * 128 + lane * 4;
                la[v].x = (r0     < nrows) ? labels[r0]     : -1;
                la[v].y = (r0 + 1 < nrows) ? labels[r0 + 1] : -1;
                la[v].z = (r0 + 2 < nrows) ? labels[r0 + 2] : -1;
                la[v].w = (r0 + 3 < nrows) ? labels[r0 + 3] : -1;
            }
        }

        // ---- scan: build this warp's worklist ----
        int m = 0;
        #pragma unroll
        for (int v = 0; v < 4; v++) {
            int labs[4] = { la[v].x, la[v].y, la[v].z, la[v].w };
            #pragma unroll
            for (int j = 0; j < 4; j++) {
                int lab = labs[j];
                bool mine = ((unsigned)lab < 128u) && ((lab >> 3) == warp);
                unsigned msk = __ballot_sync(0xffffffffu, mine);
                if (mine) {
                    int idx = m + __popc(msk & lt);
                    if (idx < WLMAX)
                        wl[idx] = ((v * 128 + lane * 4 + j) << 8) | lab;
                }
                m += __popc(msk);
            }
        }
        if (m > WLMAX) m = WLMAX;
        __syncwarp();
        if (m == 0) continue;

        // ---- counting sort of wl[0..m) by class (3 low bits), 3 slots/lane ----
        {
            int es0 = (lane      < m) ? wl[lane]      : -1;
            int es1 = (lane + 32 < m) ? wl[lane + 32] : -1;
            int es2 = (lane + 64 < m) ? wl[lane + 64] : -1;
            int k0 = (es0 >= 0) ? (es0 & 7) : 8;
            int k1 = (es1 >= 0) ? (es1 & 7) : 8;
            int k2 = (es2 >= 0) ? (es2 & 7) : 8;
            int r0 = -1, r1 = -1, r2 = -1;
            int off = 0;
            #pragma unroll
            for (int c = 0; c < 8; c++) {
                unsigned b0 = __ballot_sync(0xffffffffu, k0 == c);
                unsigned b1 = __ballot_sync(0xffffffffu, k1 == c);
                unsigned b2 = __ballot_sync(0xffffffffu, k2 == c);
                int p0 = __popc(b0), p1 = __popc(b1);
                if (k0 == c) r0 = off + __popc(b0 & lt);
                if (k1 == c) r1 = off + p0 + __popc(b1 & lt);
                if (k2 == c) r2 = off + p0 + p1 + __popc(b2 & lt);
                off += p0 + p1 + __popc(b2);
            }
            __syncwarp();
            if (r0 >= 0) wl[r0] = es0;
            if (r1 >= 0) wl[r1] = es1;
            if (r2 >= 0) wl[r2] = es2;
            __syncwarp();
        }

        // ---- trash pad (row 0, class 128; merges into never-flushed slot) ----
        const int mpad = (m + 7) & ~7;
        {
            int j2 = m + lane;
            if (j2 < mpad + 8) wl[j2] = 128;
        }
        __syncwarp();

        // ---- consume: branch-free depth-4 pipeline, run-merged registers ----
        const int Ph = mpad >> 1;        // multiple of 4; half hw gets [hw*Ph, hw*Ph+Ph)
        const int hb = hw * Ph;
        float4 q0, q1, q2, q3;
        int e0, e1, e2, e3;

#define FETCH(s, p) do { e##s = wl[(p) + hb]; \
        q##s = __ldcs(&z4[(size_t)(rowbase + (e##s >> 8)) * 16 + hl]); } while (0)
#define CONSUME(s) do { \
        int kk = e##s & 255; \
        if (kk != curk) { FLUSH(); curk = kk; } \
        racc.x += q##s.x; racc.y += q##s.y; racc.z += q##s.z; racc.w += q##s.w; \
        rssq += q##s.x * q##s.x + q##s.y * q##s.y \
              + q##s.z * q##s.z + q##s.w * q##s.w; \
        rcnt += 1.f; \
        FETCH(s, i + 4 + s); } while (0)

        FETCH(0, 0); FETCH(1, 1); FETCH(2, 2); FETCH(3, 3);
        for (int i = 0; i < Ph; i += 4) {
            CONSUME(0); CONSUME(1); CONSUME(2); CONSUME(3);
        }
#undef FETCH
#undef CONSUME
    }
    FLUSH();   // final pending run
#undef FLUSH

    // ---- flush CTA partials (classes 0..127; trash class 128 dropped) ----
    __syncthreads();
    float* Pp = g_part + blockIdx.x * PART_STRIDE;
    float4* P4 = (float4*)Pp;
    for (int idx = tid; idx < KCLS * 16; idx += NTH) {
        int k = idx >> 4, h = idx & 15;
        float4 a = acc4[k * 16 + h];
        float4 b = acc4[(129 + k) * 16 + h];
        a.x += b.x; a.y += b.y; a.z += b.z; a.w += b.w;
        P4[k * 16 + h] = a;
    }
    if (tid < KCLS) {
        float s = 0.f;
        #pragma unroll
        for (int h = 0; h < 16; h++)
            s += acc2[tid * 16 + h] + acc2[(129 + tid) * 16 + h];
        Pp[8192 + tid] = scnt[tid] + scnt[130 + tid];
        Pp[8320 + tid] = s;
    }
}

// ================= per-class reduction =================
__global__ void __launch_bounds__(256) k_mid() {
    const int k = blockIdx.x;
    const int t = threadIdx.x;
    __shared__ float sred[256];
    __shared__ float wcn[8], wsq[8];
    __shared__ float sc[2];
    __shared__ float sq2r[2];

    const int d = t & 63, g = t >> 6;
    float s = 0.f;
    for (int c = g; c < GRID_MAIN; c += 4)
        s += g_part[c * PART_STRIDE + k * 64 + d];
    sred[t] = s;

    float cn = 0.f, sq = 0.f;
    for (int c = t; c < GRID_MAIN; c += 256) {
        cn += g_part[c * PART_STRIDE + 8192 + k];
        sq += g_part[c * PART_STRIDE + 8320 + k];
    }
    #pragma unroll
    for (int o = 16; o; o >>= 1) {
        cn += __shfl_down_sync(0xffffffffu, cn, o);
        sq += __shfl_down_sync(0xffffffffu, sq, o);
    }
    if ((t & 31) == 0) { wcn[t >> 5] = cn; wsq[t >> 5] = sq; }
    __syncthreads();

    if (t == 0) {
        float c0 = 0.f, s0 = 0.f;
        #pragma unroll
        for (int w = 0; w < 8; w++) { c0 += wcn[w]; s0 += wsq[w]; }
        sc[0] = c0; sc[1] = s0;
    }
    __syncthreads();

    const float cnt = sc[0], ssq = sc[1];
    const float safe = fmaxf(cnt, 1.f);

    float sq2 = 0.f;
    if (t < 64) {
        float sum = sred[t] + sred[t + 64] + sred[t + 128] + sred[t + 192];
        float cd = sum / safe;
        g_centers[k * 64 + t] = cd;
        sq2 = cd * cd;
    }
    #pragma unroll
    for (int o = 16; o; o >>= 1) sq2 += __shfl_down_sync(0xffffffffu, sq2, o);
    if (t == 0)  sq2r[0] = sq2;
    if (t == 32) sq2r[1] = sq2;
    __syncthreads();

    if (t == 0) {
        float sqn = sq2r[0] + sq2r[1];
        g_sqn[k] = sqn;
        g_cntk[k] = cnt;
        float var = ssq / safe - sqn;
        if (cnt > 1.f) { atomicAdd(&g_ivar, var); atomicAdd(&g_nh2, 1.f); }
        if (cnt > 0.f) atomicAdd(&g_nvalid, 1.f);
    }
}

// ================= pairwise distances + final loss =================
__global__ void __launch_bounds__(256) k_pair(float* __restrict__ out) {
    __shared__ float c[KCLS * 65];
    __shared__ float cnts[KCLS];
    __shared__ float sqns[KCLS];
    __shared__ float red[256];

    const int t = threadIdx.x;
    for (int idx = t; idx < KCLS * DDIM; idx += 256)
        c[(idx >> 6) * 65 + (idx & 63)] = g_centers[idx];
    if (t < KCLS) { cnts[t] = g_cntk[t]; sqns[t] = g_sqn[t]; }
    __syncthreads();

    float dsum = 0.f, pcnt = 0.f;
    for (int p = blockIdx.x * 256 + t; p < KCLS * KCLS; p += PAIRBLKS * 256) {
        int i = p >> 7, j = p & 127;
        if (j > i && cnts[i] > 0.f && cnts[j] > 0.f) {
            float d0 = 0.f, d1 = 0.f;
            #pragma unroll
            for (int d = 0; d < DDIM; d += 2) {
                d0 = fmaf(c[i * 65 + d],     c[j * 65 + d],     d0);
                d1 = fmaf(c[i * 65 + d + 1], c[j * 65 + d + 1], d1);
            }
            float sq = sqns[i] + sqns[j] - 2.f * (d0 + d1);
            dsum += sqrtf(fmaxf(sq, 0.f));
            pcnt += 1.f;
        }
    }

    red[t] = dsum; __syncthreads();
    for (int s = 128; s; s >>= 1) { if (t < s) red[t] += red[t + s]; __syncthreads(); }
    if (t == 0) atomicAdd(&g_dsum, red[0]);
    __syncthreads();
    red[t] = pcnt; __syncthreads();
    for (int s = 128; s; s >>= 1) { if (t < s) red[t] += red[t + s]; __syncthreads(); }

    if (t == 0) {
        atomicAdd(&g_pcnt, red[0]);
        __threadfence();
        unsigned tk = atomicAdd(&g_ticket, 1u);
        if (tk == PAIRBLKS - 1) {
            float nh2 = g_nh2, nvalid = g_nvalid, ivar = g_ivar;
            float dT = g_dsum, pT = g_pcnt;
            float intra = (nh2 > 0.f) ? ivar / nh2 : 0.f;
            float inter = (pT > 0.f) ? -dT / pT : 0.f;
            float loss = intra + 0.5f * inter;
            out[0] = (nvalid >= 2.f) ? loss : 0.f;
        }
    }
}

// ================= launch =================
extern "C" void kernel_launch(void* const* d_in, const int* in_sizes, int n_in,
                              void* d_out, int out_size) {
    const float4* z4 = (const float4*)d_in[0];
    const int* labels = (const int*)d_in[1];
    int nrows = in_sizes[0] / DDIM;

    cudaFuncSetAttribute(k_main, cudaFuncAttributeMaxDynamicSharedMemorySize,
                         SMEM_MAIN);

    k_main<<<GRID_MAIN, NTH, SMEM_MAIN>>>(z4, labels, nrows);
    k_mid<<<KCLS, 256>>>();
    k_pair<<<PAIRBLKS, 256>>>((float*)d_out);
}

// round 11
// speedup vs baseline: 1.1086x; 1.0431x over previous
#include <cuda_runtime.h>

#define KCLS   128
#define DDIM   64
#define BROWS  512
#define NTH    512
#define NWARP  16
#define GRID_MAIN 304
#define PART_STRIDE 8448        // 8192 sums + 128 cnt + 128 ssq
#define PAIRBLKS 16
#define WLCAP  112
#define WLMAX  96

// dynamic smem layout for k_main (bytes)
#define OFF_ACC4  0             // float4[2][129][16] = 66048
#define OFF_ACC2  66048         // float [2][129][16] = 16512
#define OFF_CNT   82560         // float [2][130]     = 1040
#define OFF_WL    83600         // int   [16][112]    = 7168
#define SMEM_MAIN 90768

__device__ float g_part[GRID_MAIN * PART_STRIDE];
__device__ float g_centers[KCLS * DDIM];
__device__ float g_sqn[KCLS];
__device__ float g_cntk[KCLS];
__device__ float g_ivar, g_nh2, g_nvalid, g_dsum, g_pcnt;
__device__ unsigned g_ticket;

// ================= main accumulation =================
__global__ void __launch_bounds__(NTH, 2)
k_main(const float4* __restrict__ z4, const int* __restrict__ labels, int nrows) {
    extern __shared__ char sm[];
    float4* acc4 = (float4*)(sm + OFF_ACC4);
    float*  acc2 = (float*) (sm + OFF_ACC2);
    float*  scnt = (float*) (sm + OFF_CNT);
    int*    wlist= (int*)   (sm + OFF_WL);

    const int tid  = threadIdx.x;
    const int warp = tid >> 5;
    const int lane = tid & 31;
    const int hw   = lane >> 4;
    const int hl   = lane & 15;
    const unsigned lt = (1u << lane) - 1u;
    int* wl = wlist + warp * WLCAP;

    if (blockIdx.x == 0 && tid == 0) {
        g_ivar = 0.f; g_nh2 = 0.f; g_nvalid = 0.f;
        g_dsum = 0.f; g_pcnt = 0.f; g_ticket = 0u;
    }

    // zero accumulators (83600 B = 5225 float4)
    {
        float4* p = (float4*)sm;
        const float4 zz = make_float4(0.f, 0.f, 0.f, 0.f);
        for (int i = tid; i < 5225; i += NTH) p[i] = zz;
    }
    __syncthreads();   // last CTA-wide sync until flush

    const int nb = (nrows + BROWS - 1) / BROWS;

    // run-merged register accumulator (persists across tiles)
    float4 racc = make_float4(0.f, 0.f, 0.f, 0.f);
    float rssq = 0.f, rcnt = 0.f;
    int curk = -1;

#define FLUSH() do { if (curk >= 0) { \
        int ci = hw * 129 + curk; \
        int ai = ci * 16 + hl; \
        float4 t = acc4[ai]; \
        t.x += racc.x; t.y += racc.y; t.z += racc.z; t.w += racc.w; \
        acc4[ai] = t; \
        acc2[ai] += rssq; \
        if (hl == 0) scnt[hw * 130 + curk] += rcnt; \
        racc = make_float4(0.f, 0.f, 0.f, 0.f); rssq = 0.f; rcnt = 0.f; \
    } } while (0)

    for (int tile = blockIdx.x; tile < nb; tile += GRID_MAIN) {
        const int rowbase = tile * BROWS;

        // ---- labels (int4 vectorized; scalar-guarded only on the last tile) ----
        int4 la[4];
        if (rowbase + BROWS <= nrows) {
            const int4* lab4 = (const int4*)(labels + rowbase);
            #pragma unroll
            for (int v = 0; v < 4; v++) la[v] = lab4[v * 32 + lane];
        } else {
            #pragma unroll
            for (int v = 0; v < 4; v++) {
                int r0 = rowbase + v * 128 + lane * 4;
                la[v].x = (r0     < nrows) ? labels[r0]     : -1;
                la[v].y = (r0 + 1 < nrows) ? labels[r0 + 1] : -1;
                la[v].z = (r0 + 2 < nrows) ? labels[r0 + 2] : -1;
                la[v].w = (r0 + 3 < nrows) ? labels[r0 + 3] : -1;
            }
        }

        // ---- scan: build this warp's worklist ----
        int m = 0;
        #pragma unroll
        for (int v = 0; v < 4; v++) {
            int labs[4] = { la[v].x, la[v].y, la[v].z, la[v].w };
            #pragma unroll
            for (int j = 0; j < 4; j++) {
                int lab = labs[j];
                bool mine = ((unsigned)lab < 128u) && ((lab >> 3) == warp);
                unsigned msk = __ballot_sync(0xffffffffu, mine);
                if (mine) {
                    int idx = m + __popc(msk & lt);
                    if (idx < WLMAX)
                        wl[idx] = ((v * 128 + lane * 4 + j) << 8) | lab;
                }
                m += __popc(msk);
            }
        }
        if (m > WLMAX) m = WLMAX;
        __syncwarp();
        if (m == 0) continue;

        // ---- counting sort of wl[0..m) by class (3 low bits), 3 slots/lane ----
        {
            int es0 = (lane      < m) ? wl[lane]      : -1;
            int es1 = (lane + 32 < m) ? wl[lane + 32] : -1;
            int es2 = (lane + 64 < m) ? wl[lane + 64] : -1;
            int k0 = (es0 >= 0) ? (es0 & 7) : 8;
            int k1 = (es1 >= 0) ? (es1 & 7) : 8;
            int k2 = (es2 >= 0) ? (es2 & 7) : 8;
            int r0 = -1, r1 = -1, r2 = -1;
            int off = 0;
            #pragma unroll
            for (int c = 0; c < 8; c++) {
                unsigned b0 = __ballot_sync(0xffffffffu, k0 == c);
                unsigned b1 = __ballot_sync(0xffffffffu, k1 == c);
                unsigned b2 = __ballot_sync(0xffffffffu, k2 == c);
                int p0 = __popc(b0), p1 = __popc(b1);
                if (k0 == c) r0 = off + __popc(b0 & lt);
                if (k1 == c) r1 = off + p0 + __popc(b1 & lt);
                if (k2 == c) r2 = off + p0 + p1 + __popc(b2 & lt);
                off += p0 + p1 + __popc(b2);
            }
            __syncwarp();
            if (r0 >= 0) wl[r0] = es0;
            if (r1 >= 0) wl[r1] = es1;
            if (r2 >= 0) wl[r2] = es2;
            __syncwarp();
        }

        // ---- trash pad to multiple of 10 (+depth lookahead) ----
        const int mpad = ((m + 9) / 10) * 10;
        {
            int j2 = m + lane;
            if (j2 < mpad + 10) wl[j2] = 128;   // row 0, trash class 128
        }
        __syncwarp();

        // ---- consume: branch-free depth-5 pipeline, run-merged registers ----
        const int Ph = mpad >> 1;        // multiple of 5; half hw gets [hw*Ph, hw*Ph+Ph)
        const int hb = hw * Ph;
        const float4* zt = z4 + (size_t)rowbase * 16 + hl;
        float4 q0, q1, q2, q3, q4;
        int e0, e1, e2, e3, e4;

#define FETCH(s, p) do { e##s = wl[(p) + hb]; \
        q##s = __ldcs(&zt[(size_t)((unsigned)e##s >> 8) * 16]); } while (0)
#define CONSUME(s) do { \
        int kk = e##s & 255; \
        if (kk != curk) { FLUSH(); curk = kk; } \
        racc.x += q##s.x; racc.y += q##s.y; racc.z += q##s.z; racc.w += q##s.w; \
        rssq += q##s.x * q##s.x + q##s.y * q##s.y \
              + q##s.z * q##s.z + q##s.w * q##s.w; \
        rcnt += 1.f; \
        FETCH(s, i + 5 + s); } while (0)

        FETCH(0, 0); FETCH(1, 1); FETCH(2, 2); FETCH(3, 3); FETCH(4, 4);
        for (int i = 0; i < Ph; i += 5) {
            CONSUME(0); CONSUME(1); CONSUME(2); CONSUME(3); CONSUME(4);
        }
#undef FETCH
#undef CONSUME
    }
    FLUSH();   // final pending run
#undef FLUSH

    // ---- flush CTA partials (classes 0..127; trash class 128 dropped) ----
    __syncthreads();
    float* Pp = g_part + blockIdx.x * PART_STRIDE;
    float4* P4 = (float4*)Pp;
    for (int idx = tid; idx < KCLS * 16; idx += NTH) {
        int k = idx >> 4, h = idx & 15;
        float4 a = acc4[k * 16 + h];
        float4 b = acc4[(129 + k) * 16 + h];
        a.x += b.x; a.y += b.y; a.z += b.z; a.w += b.w;
        P4[k * 16 + h] = a;
    }
    if (tid < KCLS) {
        float s = 0.f;
        #pragma unroll
        for (int h = 0; h < 16; h++)
            s += acc2[tid * 16 + h] + acc2[(129 + tid) * 16 + h];
        Pp[8192 + tid] = scnt[tid] + scnt[130 + tid];
        Pp[8320 + tid] = s;
    }
}

// ================= per-class reduction (512 threads for MLP) =================
__global__ void __launch_bounds__(512) k_mid() {
    const int k = blockIdx.x;
    const int t = threadIdx.x;
    __shared__ float sred[512];
    __shared__ float wcn[16], wsq[16];
    __shared__ float sc[2];
    __shared__ float sq2r[2];

    const int d = t & 63, g = t >> 6;        // g in 0..7
    float s = 0.f;
    for (int c = g; c < GRID_MAIN; c += 8)
        s += g_part[c * PART_STRIDE + k * 64 + d];
    sred[t] = s;

    float cn = 0.f, sq = 0.f;
    if (t < GRID_MAIN) {
        cn = g_part[t * PART_STRIDE + 8192 + k];
        sq = g_part[t * PART_STRIDE + 8320 + k];
    }
    #pragma unroll
    for (int o = 16; o; o >>= 1) {
        cn += __shfl_down_sync(0xffffffffu, cn, o);
        sq += __shfl_down_sync(0xffffffffu, sq, o);
    }
    if ((t & 31) == 0) { wcn[t >> 5] = cn; wsq[t >> 5] = sq; }
    __syncthreads();

    if (t == 0) {
        float c0 = 0.f, s0 = 0.f;
        #pragma unroll
        for (int w = 0; w < 16; w++) { c0 += wcn[w]; s0 += wsq[w]; }
        sc[0] = c0; sc[1] = s0;
    }
    __syncthreads();

    const float cnt = sc[0], ssq = sc[1];
    const float safe = fmaxf(cnt, 1.f);

    float sq2 = 0.f;
    if (t < 64) {
        float sum = 0.f;
        #pragma unroll
        for (int j = 0; j < 8; j++) sum += sred[t + 64 * j];
        float cd = sum / safe;
        g_centers[k * 64 + t] = cd;
        sq2 = cd * cd;
    }
    #pragma unroll
    for (int o = 16; o; o >>= 1) sq2 += __shfl_down_sync(0xffffffffu, sq2, o);
    if (t == 0)  sq2r[0] = sq2;
    if (t == 32) sq2r[1] = sq2;
    __syncthreads();

    if (t == 0) {
        float sqn = sq2r[0] + sq2r[1];
        g_sqn[k] = sqn;
        g_cntk[k] = cnt;
        float var = ssq / safe - sqn;
        if (cnt > 1.f) { atomicAdd(&g_ivar, var); atomicAdd(&g_nh2, 1.f); }
        if (cnt > 0.f) atomicAdd(&g_nvalid, 1.f);
    }
}

// ================= pairwise distances + final loss =================
__global__ void __launch_bounds__(256) k_pair(float* __restrict__ out) {
    __shared__ float c[KCLS * 65];
    __shared__ float cnts[KCLS];
    __shared__ float sqns[KCLS];
    __shared__ float red[256];

    const int t = threadIdx.x;
    for (int idx = t; idx < KCLS * DDIM; idx += 256)
        c[(idx >> 6) * 65 + (idx & 63)] = g_centers[idx];
    if (t < KCLS) { cnts[t] = g_cntk[t]; sqns[t] = g_sqn[t]; }
    __syncthreads();

    float dsum = 0.f, pcnt = 0.f;
    for (int p = blockIdx.x * 256 + t; p < KCLS * KCLS; p += PAIRBLKS * 256) {
        int i = p >> 7, j = p & 127;
        if (j > i && cnts[i] > 0.f && cnts[j] > 0.f) {
            float d0 = 0.f, d1 = 0.f;
            #pragma unroll
            for (int d = 0; d < DDIM; d += 2) {
                d0 = fmaf(c[i * 65 + d],     c[j * 65 + d],     d0);
                d1 = fmaf(c[i * 65 + d + 1], c[j * 65 + d + 1], d1);
            }
            float sq = sqns[i] + sqns[j] - 2.f * (d0 + d1);
            dsum += sqrtf(fmaxf(sq, 0.f));
            pcnt += 1.f;
        }
    }

    red[t] = dsum; __syncthreads();
    for (int s = 128; s; s >>= 1) { if (t < s) red[t] += red[t + s]; __syncthreads(); }
    if (t == 0) atomicAdd(&g_dsum, red[0]);
    __syncthreads();
    red[t] = pcnt; __syncthreads();
    for (int s = 128; s; s >>= 1) { if (t < s) red[t] += red[t + s]; __syncthreads(); }

    if (t == 0) {
        atomicAdd(&g_pcnt, red[0]);
        __threadfence();
        unsigned tk = atomicAdd(&g_ticket, 1u);
        if (tk == PAIRBLKS - 1) {
            float nh2 = g_nh2, nvalid = g_nvalid, ivar = g_ivar;
            float dT = g_dsum, pT = g_pcnt;
            float intra = (nh2 > 0.f) ? ivar / nh2 : 0.f;
            float inter = (pT > 0.f) ? -dT / pT : 0.f;
            float loss = intra + 0.5f * inter;
            out[0] = (nvalid >= 2.f) ? loss : 0.f;
        }
    }
}

// ================= launch =================
extern "C" void kernel_launch(void* const* d_in, const int* in_sizes, int n_in,
                              void* d_out, int out_size) {
    const float4* z4 = (const float4*)d_in[0];
    const int* labels = (const int*)d_in[1];
    int nrows = in_sizes[0] / DDIM;

    cudaFuncSetAttribute(k_main, cudaFuncAttributeMaxDynamicSharedMemorySize,
                         SMEM_MAIN);

    k_main<<<GRID_MAIN, NTH, SMEM_MAIN>>>(z4, labels, nrows);
    k_mid<<<KCLS, 512>>>();
    k_pair<<<PAIRBLKS, 256>>>((float*)d_out);
}

// round 12
// speedup vs baseline: 1.1089x; 1.0003x over previous
#include <cuda_runtime.h>

#define KCLS   128
#define DDIM   64
#define BROWS  512
#define NTH    512
#define NWARP  16
#define GRID_MAIN 304
#define PART_STRIDE 8448        // 8192 sums + 128 cnt + 128 ssq
#define PAIRBLKS 16
#define WLCAP  112
#define WLMAX  96

// dynamic smem layout for k_main (bytes)
#define OFF_ACC4  0             // float4[2][129][16] = 66048
#define OFF_ACC2  66048         // float [2][129][16] = 16512
#define OFF_CNT   82560         // float [2][130]     = 1040
#define OFF_WL    83600         // int   [16][112]    = 7168
#define SMEM_MAIN 90768

__device__ float g_part[GRID_MAIN * PART_STRIDE];
__device__ float g_centers[KCLS * DDIM];
__device__ float g_sqn[KCLS];
__device__ float g_cntk[KCLS];
__device__ float g_ivar, g_nh2, g_nvalid, g_dsum, g_pcnt;
__device__ unsigned g_ticket;

// ================= main accumulation =================
__global__ void __launch_bounds__(NTH, 2)
k_main(const float4* __restrict__ z4, const int* __restrict__ labels, int nrows) {
    extern __shared__ char sm[];
    float4* acc4 = (float4*)(sm + OFF_ACC4);
    float*  acc2 = (float*) (sm + OFF_ACC2);
    float*  scnt = (float*) (sm + OFF_CNT);
    int*    wlist= (int*)   (sm + OFF_WL);

    const int tid  = threadIdx.x;
    const int warp = tid >> 5;
    const int lane = tid & 31;
    const int hw   = lane >> 4;
    const int hl   = lane & 15;
    const unsigned lt = (1u << lane) - 1u;
    const int wbase = warp << 3;    // first class owned by this warp
    int* wl = wlist + warp * WLCAP;

    if (blockIdx.x == 0 && tid == 0) {
        g_ivar = 0.f; g_nh2 = 0.f; g_nvalid = 0.f;
        g_dsum = 0.f; g_pcnt = 0.f; g_ticket = 0u;
    }

    // zero accumulators (83600 B = 5225 float4)
    {
        float4* p = (float4*)sm;
        const float4 zz = make_float4(0.f, 0.f, 0.f, 0.f);
        for (int i = tid; i < 5225; i += NTH) p[i] = zz;
    }
    __syncthreads();   // last CTA-wide sync until flush

    const int nb = (nrows + BROWS - 1) / BROWS;

    // run-merged register accumulator (persists across tiles)
    float4 racc = make_float4(0.f, 0.f, 0.f, 0.f);
    float rssq = 0.f, rcnt = 0.f;
    int curk = -1;

#define FLUSH() do { if (curk >= 0) { \
        int ci = hw * 129 + curk; \
        int ai = ci * 16 + hl; \
        float4 t = acc4[ai]; \
        t.x += racc.x; t.y += racc.y; t.z += racc.z; t.w += racc.w; \
        acc4[ai] = t; \
        acc2[ai] += rssq; \
        if (hl == 0) scnt[hw * 130 + curk] += rcnt; \
        racc = make_float4(0.f, 0.f, 0.f, 0.f); rssq = 0.f; rcnt = 0.f; \
    } } while (0)

    for (int tile = blockIdx.x; tile < nb; tile += GRID_MAIN) {
        const int rowbase = tile * BROWS;

        // ---- labels (int4 vectorized; scalar-guarded only on the last tile) ----
        int4 la[4];
        if (rowbase + BROWS <= nrows) {
            const int4* lab4 = (const int4*)(labels + rowbase);
            #pragma unroll
            for (int v = 0; v < 4; v++) la[v] = lab4[v * 32 + lane];
        } else {
            #pragma unroll
            for (int v = 0; v < 4; v++) {
                int r0 = rowbase + v * 128 + lane * 4;
                la[v].x = (r0     < nrows) ? labels[r0]     : -1;
                la[v].y = (r0 + 1 < nrows) ? labels[r0 + 1] : -1;
                la[v].z = (r0 + 2 < nrows) ? labels[r0 + 2] : -1;
                la[v].w = (r0 + 3 < nrows) ? labels[r0 + 3] : -1;
            }
        }

        // ---- scan: build this warp's worklist ----
        int m = 0;
        #pragma unroll
        for (int v = 0; v < 4; v++) {
            int labs[4] = { la[v].x, la[v].y, la[v].z, la[v].w };
            #pragma unroll
            for (int j = 0; j < 4; j++) {
                int lab = labs[j];
                bool mine = ((unsigned)(lab - wbase) < 8u);   // negatives/>=128 wrap out
                unsigned msk = __ballot_sync(0xffffffffu, mine);
                if (mine) {
                    int idx = m + __popc(msk & lt);
                    if (idx < WLMAX)
                        wl[idx] = ((v * 128 + lane * 4 + j) << 8) | lab;
                }
                m += __popc(msk);
            }
        }
        if (m > WLMAX) m = WLMAX;
        __syncwarp();
        if (m == 0) continue;

        // ---- counting sort of wl[0..m) by class (3 low bits), 3 slots/lane ----
        {
            int es0 = (lane      < m) ? wl[lane]      : -1;
            int es1 = (lane + 32 < m) ? wl[lane + 32] : -1;
            int es2 = (lane + 64 < m) ? wl[lane + 64] : -1;
            int k0 = (es0 >= 0) ? (es0 & 7) : 8;
            int k1 = (es1 >= 0) ? (es1 & 7) : 8;
            int k2 = (es2 >= 0) ? (es2 & 7) : 8;
            int r0 = -1, r1 = -1, r2 = -1;
            int off = 0;
            #pragma unroll
            for (int c = 0; c < 8; c++) {
                unsigned b0 = __ballot_sync(0xffffffffu, k0 == c);
                unsigned b1 = __ballot_sync(0xffffffffu, k1 == c);
                unsigned b2 = __ballot_sync(0xffffffffu, k2 == c);
                int p0 = __popc(b0), p1 = __popc(b1);
                if (k0 == c) r0 = off + __popc(b0 & lt);
                if (k1 == c) r1 = off + p0 + __popc(b1 & lt);
                if (k2 == c) r2 = off + p0 + p1 + __popc(b2 & lt);
                off += p0 + p1 + __popc(b2);
            }
            __syncwarp();
            if (r0 >= 0) wl[r0] = es0;
            if (r1 >= 0) wl[r1] = es1;
            if (r2 >= 0) wl[r2] = es2;
            __syncwarp();
        }

        // ---- trash pad to multiple of 10 (+depth lookahead) ----
        const int mpad = ((m + 9) / 10) * 10;
        {
            int j2 = m + lane;
            if (j2 < mpad + 10) wl[j2] = 128;   // row 0, trash class 128
        }
        __syncwarp();

        // ---- consume: branch-free depth-5 pipeline, run-merged registers ----
        // wl entry e = row*256 + lab; z row is 256 bytes, so byte offset = e & ~255.
        const int Ph = mpad >> 1;        // multiple of 5; half hw gets [hw*Ph, hw*Ph+Ph)
        const int hb = hw * Ph;
        const char* ztb = (const char*)(z4 + (size_t)rowbase * 16 + hl);
        float4 q0, q1, q2, q3, q4;
        int e0, e1, e2, e3, e4;

#define FETCH(s, p) do { e##s = wl[(p) + hb]; \
        q##s = __ldcs((const float4*)(ztb + ((unsigned)e##s & 0xFFFFFF00u))); } while (0)
#define CONSUME(s) do { \
        int kk = e##s & 255; \
        if (kk != curk) { FLUSH(); curk = kk; } \
        racc.x += q##s.x; racc.y += q##s.y; racc.z += q##s.z; racc.w += q##s.w; \
        rssq += q##s.x * q##s.x + q##s.y * q##s.y \
              + q##s.z * q##s.z + q##s.w * q##s.w; \
        rcnt += 1.f; \
        FETCH(s, i + 5 + s); } while (0)

        FETCH(0, 0); FETCH(1, 1); FETCH(2, 2); FETCH(3, 3); FETCH(4, 4);
        for (int i = 0; i < Ph; i += 5) {
            CONSUME(0); CONSUME(1); CONSUME(2); CONSUME(3); CONSUME(4);
        }
#undef FETCH
#undef CONSUME
    }
    FLUSH();   // final pending run
#undef FLUSH

    // ---- flush CTA partials (classes 0..127; trash class 128 dropped) ----
    __syncthreads();
    float* Pp = g_part + blockIdx.x * PART_STRIDE;
    float4* P4 = (float4*)Pp;
    for (int idx = tid; idx < KCLS * 16; idx += NTH) {
        int k = idx >> 4, h = idx & 15;
        float4 a = acc4[k * 16 + h];
        float4 b = acc4[(129 + k) * 16 + h];
        a.x += b.x; a.y += b.y; a.z += b.z; a.w += b.w;
        P4[k * 16 + h] = a;
    }
    if (tid < KCLS) {
        float s = 0.f;
        #pragma unroll
        for (int h = 0; h < 16; h++)
            s += acc2[tid * 16 + h] + acc2[(129 + tid) * 16 + h];
        Pp[8192 + tid] = scnt[tid] + scnt[130 + tid];
        Pp[8320 + tid] = s;
    }
}

// ================= per-class reduction (512 threads for MLP) =================
__global__ void __launch_bounds__(512) k_mid() {
    const int k = blockIdx.x;
    const int t = threadIdx.x;
    __shared__ float sred[512];
    __shared__ float wcn[16], wsq[16];
    __shared__ float sc[2];
    __shared__ float sq2r[2];

    const int d = t & 63, g = t >> 6;        // g in 0..7
    float s = 0.f;
    for (int c = g; c < GRID_MAIN; c += 8)
        s += g_part[c * PART_STRIDE + k * 64 + d];
    sred[t] = s;

    float cn = 0.f, sq = 0.f;
    if (t < GRID_MAIN) {
        cn = g_part[t * PART_STRIDE + 8192 + k];
        sq = g_part[t * PART_STRIDE + 8320 + k];
    }
    #pragma unroll
    for (int o = 16; o; o >>= 1) {
        cn += __shfl_down_sync(0xffffffffu, cn, o);
        sq += __shfl_down_sync(0xffffffffu, sq, o);
    }
    if ((t & 31) == 0) { wcn[t >> 5] = cn; wsq[t >> 5] = sq; }
    __syncthreads();

    if (t == 0) {
        float c0 = 0.f, s0 = 0.f;
        #pragma unroll
        for (int w = 0; w < 16; w++) { c0 += wcn[w]; s0 += wsq[w]; }
        sc[0] = c0; sc[1] = s0;
    }
    __syncthreads();

    const float cnt = sc[0], ssq = sc[1];
    const float safe = fmaxf(cnt, 1.f);

    float sq2 = 0.f;
    if (t < 64) {
        float sum = 0.f;
        #pragma unroll
        for (int j = 0; j < 8; j++) sum += sred[t + 64 * j];
        float cd = sum / safe;
        g_centers[k * 64 + t] = cd;
        sq2 = cd * cd;
    }
    #pragma unroll
    for (int o = 16; o; o >>= 1) sq2 += __shfl_down_sync(0xffffffffu, sq2, o);
    if (t == 0)  sq2r[0] = sq2;
    if (t == 32) sq2r[1] = sq2;
    __syncthreads();

    if (t == 0) {
        float sqn = sq2r[0] + sq2r[1];
        g_sqn[k] = sqn;
        g_cntk[k] = cnt;
        float var = ssq / safe - sqn;
        if (cnt > 1.f) { atomicAdd(&g_ivar, var); atomicAdd(&g_nh2, 1.f); }
        if (cnt > 0.f) atomicAdd(&g_nvalid, 1.f);
    }
}

// ================= pairwise distances + final loss =================
__global__ void __launch_bounds__(256) k_pair(float* __restrict__ out) {
    __shared__ float c[KCLS * 65];
    __shared__ float cnts[KCLS];
    __shared__ float sqns[KCLS];
    __shared__ float red[256];

    const int t = threadIdx.x;
    for (int idx = t; idx < KCLS * DDIM; idx += 256)
        c[(idx >> 6) * 65 + (idx & 63)] = g_centers[idx];
    if (t < KCLS) { cnts[t] = g_cntk[t]; sqns[t] = g_sqn[t]; }
    __syncthreads();

    float dsum = 0.f, pcnt = 0.f;
    for (int p = blockIdx.x * 256 + t; p < KCLS * KCLS; p += PAIRBLKS * 256) {
        int i = p >> 7, j = p & 127;
        if (j > i && cnts[i] > 0.f && cnts[j] > 0.f) {
            float d0 = 0.f, d1 = 0.f;
            #pragma unroll
            for (int d = 0; d < DDIM; d += 2) {
                d0 = fmaf(c[i * 65 + d],     c[j * 65 + d],     d0);
                d1 = fmaf(c[i * 65 + d + 1], c[j * 65 + d + 1], d1);
            }
            float sq = sqns[i] + sqns[j] - 2.f * (d0 + d1);
            dsum += sqrtf(fmaxf(sq, 0.f));
            pcnt += 1.f;
        }
    }

    red[t] = dsum; __syncthreads();
    for (int s = 128; s; s >>= 1) { if (t < s) red[t] += red[t + s]; __syncthreads(); }
    if (t == 0) atomicAdd(&g_dsum, red[0]);
    __syncthreads();
    red[t] = pcnt; __syncthreads();
    for (int s = 128; s; s >>= 1) { if (t < s) red[t] += red[t + s]; __syncthreads(); }

    if (t == 0) {
        atomicAdd(&g_pcnt, red[0]);
        __threadfence();
        unsigned tk = atomicAdd(&g_ticket, 1u);
        if (tk == PAIRBLKS - 1) {
            float nh2 = g_nh2, nvalid = g_nvalid, ivar = g_ivar;
            float dT = g_dsum, pT = g_pcnt;
            float intra = (nh2 > 0.f) ? ivar / nh2 : 0.f;
            float inter = (pT > 0.f) ? -dT / pT : 0.f;
            float loss = intra + 0.5f * inter;
            out[0] = (nvalid >= 2.f) ? loss : 0.f;
        }
    }
}

// ================= launch =================
extern "C" void kernel_launch(void* const* d_in, const int* in_sizes, int n_in,
                              void* d_out, int out_size) {
    const float4* z4 = (const float4*)d_in[0];
    const int* labels = (const int*)d_in[1];
    int nrows = in_sizes[0] / DDIM;

    cudaFuncSetAttribute(k_main, cudaFuncAttributeMaxDynamicSharedMemorySize,
                         SMEM_MAIN);

    k_main<<<GRID_MAIN, NTH, SMEM_MAIN>>>(z4, labels, nrows);
    k_mid<<<KCLS, 512>>>();
    k_pair<<<PAIRBLKS, 256>>>((float*)d_out);
}